// round 3
// baseline (speedup 1.0000x reference)
#include <cuda_runtime.h>
#include <cstdint>

#define NN 8192
#define RPB 4                 // rows per CTA
#define TPB 256
#define STAGES 2
#define JW (TPB * 4)          // j-elements per stage (each thread: one int4 per row)
#define NSTAGES (NN / JW)     // 8 stages per CTA

// Scratch (device globals — no allocation allowed in kernel_launch)
__device__ float g_s[NN];
__device__ float g_wmax[NN];
__device__ float g_wmin[NN];

__global__ void precompute_kernel(const float* __restrict__ x,
                                  const float* __restrict__ Wphi) {
    int j = blockIdx.x * blockDim.x + threadIdx.x;
    if (j < NN) {
        g_s[j] = x[j * 3 + 0] + x[j * 3 + 1] + x[j * 3 + 2];
        float w0 = Wphi[j];
        float w1 = Wphi[NN + j];
        float w2 = Wphi[2 * NN + j];
        g_wmax[j] = fmaxf(w0, fmaxf(w1, w2));
        g_wmin[j] = fminf(w0, fminf(w1, w2));
    }
}

__device__ __forceinline__ void cp_async16(void* smem_dst, const void* gmem_src) {
    uint32_t d = (uint32_t)__cvta_generic_to_shared(smem_dst);
    asm volatile("cp.async.cg.shared.global [%0], [%1], 16;\n" :: "r"(d), "l"(gmem_src));
}

__global__ __launch_bounds__(TPB, 7)
void rowmax_kernel(const int* __restrict__ adj, float* __restrict__ out) {
    // [stage][row][thread] int4 — conflict-free for 16B LDS/STS (16B stride across lanes)
    __shared__ int4 buf[STAGES][RPB][TPB];

    const int row0 = blockIdx.x * RPB;
    const int t = threadIdx.x;

    float si[RPB], m[RPB];
    #pragma unroll
    for (int r = 0; r < RPB; r++) {
        si[r] = g_s[row0 + r];
        m[r] = 0.0f;              // reference max always includes T[i,i] = 0
    }

    const float4* s4  = reinterpret_cast<const float4*>(g_s);
    const float4* wx4 = reinterpret_cast<const float4*>(g_wmax);
    const float4* wn4 = reinterpret_cast<const float4*>(g_wmin);
    const int4*   a4  = reinterpret_cast<const int4*>(adj);

    // Issue one stage of adjacency copies (4 rows x 16B per thread), one commit group
    auto issue = [&](int st) {
        const int jb = st * TPB + t;             // int4 index within row
        #pragma unroll
        for (int r = 0; r < RPB; r++)
            cp_async16(&buf[st % STAGES][r][t],
                       a4 + (size_t)(row0 + r) * (NN / 4) + jb);
        asm volatile("cp.async.commit_group;\n" ::: "memory");
    };

    issue(0);

    for (int st = 0; st < NSTAGES; st++) {
        if (st + 1 < NSTAGES) {
            issue(st + 1);
            asm volatile("cp.async.wait_group 1;\n" ::: "memory");
        } else {
            asm volatile("cp.async.wait_group 0;\n" ::: "memory");
        }

        const int jb = st * TPB + t;
        float4 sv = s4[jb];
        float4 wx = wx4[jb];
        float4 wn = wn4[jb];

        float d0x = si[0], d1x, d2x, d3x;  // (placeholders; per-row below)
        #pragma unroll
        for (int r = 0; r < RPB; r++) {
            int4 a = buf[st % STAGES][r][t];   // this thread's own copied bytes
            float d0 = si[r] - sv.x;
            float d1 = si[r] - sv.y;
            float d2 = si[r] - sv.z;
            float d3 = si[r] - sv.w;
            if (a.x) m[r] = fmaxf(m[r], fmaxf(d0 * wx.x, d0 * wn.x));
            if (a.y) m[r] = fmaxf(m[r], fmaxf(d1 * wx.y, d1 * wn.y));
            if (a.z) m[r] = fmaxf(m[r], fmaxf(d2 * wx.z, d2 * wn.z));
            if (a.w) m[r] = fmaxf(m[r], fmaxf(d3 * wx.w, d3 * wn.w));
        }
        (void)d0x; (void)d1x; (void)d2x; (void)d3x;
    }

    // Intra-warp max per row
    #pragma unroll
    for (int r = 0; r < RPB; r++) {
        #pragma unroll
        for (int off = 16; off; off >>= 1)
            m[r] = fmaxf(m[r], __shfl_xor_sync(0xffffffffu, m[r], off));
    }

    // Cross-warp: 8 warps x RPB rows
    __shared__ float smax[TPB / 32][RPB];
    const int warp = t >> 5;
    if ((t & 31) == 0) {
        #pragma unroll
        for (int r = 0; r < RPB; r++) smax[warp][r] = m[r];
    }
    __syncthreads();

    if (t < (TPB / 32) * RPB) {               // 32 threads
        const int r = t >> 3;                 // row within CTA
        const int w = t & 7;                  // warp slot
        float v = smax[w][r];
        #pragma unroll
        for (int off = 4; off; off >>= 1)
            v = fmaxf(v, __shfl_xor_sync(0xffffffffu, v, off));
        if (w == 0) {
            const int i = row0 + r;
            out[i * 3 + 0] = v;
            out[i * 3 + 1] = v;
            out[i * 3 + 2] = v;
        }
    }
}

extern "C" void kernel_launch(void* const* d_in, const int* in_sizes, int n_in,
                              void* d_out, int out_size) {
    const float* x    = (const float*)d_in[0];
    const int*   adj  = (const int*)d_in[1];
    const float* Wphi = (const float*)d_in[2];
    // d_in[3] (W_theta) is unused in the forward pass.
    float* out = (float*)d_out;

    precompute_kernel<<<(NN + 255) / 256, 256>>>(x, Wphi);
    rowmax_kernel<<<NN / RPB, TPB>>>(adj, out);
}

// round 4
// speedup vs baseline: 1.0345x; 1.0345x over previous
#include <cuda_runtime.h>

#define NN 8192
#define RPB 8           // rows per CTA
#define TPB 256

// Scratch (device globals — no allocation allowed in kernel_launch)
__device__ float g_s[NN];
__device__ float g_wmax[NN];
__device__ float g_wmin[NN];

__global__ void precompute_kernel(const float* __restrict__ x,
                                  const float* __restrict__ Wphi) {
    int j = blockIdx.x * blockDim.x + threadIdx.x;
    if (j < NN) {
        g_s[j] = x[j * 3 + 0] + x[j * 3 + 1] + x[j * 3 + 2];
        float w0 = Wphi[j];
        float w1 = Wphi[NN + j];
        float w2 = Wphi[2 * NN + j];
        g_wmax[j] = fmaxf(w0, fmaxf(w1, w2));
        g_wmin[j] = fminf(w0, fminf(w1, w2));
    }
}

__global__ __launch_bounds__(TPB)
void rowmax_kernel(const int* __restrict__ adj, float* __restrict__ out) {
    const int row0 = blockIdx.x * RPB;

    float si[RPB], m[RPB];
    #pragma unroll
    for (int r = 0; r < RPB; r++) {
        si[r] = g_s[row0 + r];
        m[r] = 0.0f;                       // ref max always includes T[i,i]=0
    }

    const float4* s4  = reinterpret_cast<const float4*>(g_s);
    const float4* wx4 = reinterpret_cast<const float4*>(g_wmax);
    const float4* wn4 = reinterpret_cast<const float4*>(g_wmin);

    // NN/4 = 2048 int4 chunks; TPB threads -> 8 iterations
    #pragma unroll
    for (int it = 0; it < (NN / 4) / TPB; it++) {
        const int jb = it * TPB + threadIdx.x;

        // Cached float streams: loaded once per iteration for all RPB rows
        float4 sv = s4[jb];
        float4 wx = wx4[jb];
        float4 wn = wn4[jb];

        // Adjacency: streaming (evict-first) loads, front-batched for MLP.
        int4 a[RPB];
        #pragma unroll
        for (int r = 0; r < RPB; r++)
            a[r] = __ldcs(reinterpret_cast<const int4*>(adj + (size_t)(row0 + r) * NN) + jb);

        #pragma unroll
        for (int r = 0; r < RPB; r++) {
            float d0 = si[r] - sv.x;
            float d1 = si[r] - sv.y;
            float d2 = si[r] - sv.z;
            float d3 = si[r] - sv.w;
            if (a[r].x) m[r] = fmaxf(m[r], fmaxf(d0 * wx.x, d0 * wn.x));
            if (a[r].y) m[r] = fmaxf(m[r], fmaxf(d1 * wx.y, d1 * wn.y));
            if (a[r].z) m[r] = fmaxf(m[r], fmaxf(d2 * wx.z, d2 * wn.z));
            if (a[r].w) m[r] = fmaxf(m[r], fmaxf(d3 * wx.w, d3 * wn.w));
        }
    }

    // Intra-warp reduce each row's max
    #pragma unroll
    for (int r = 0; r < RPB; r++) {
        #pragma unroll
        for (int off = 16; off; off >>= 1)
            m[r] = fmaxf(m[r], __shfl_xor_sync(0xffffffffu, m[r], off));
    }

    // Cross-warp: 8 warps x RPB rows
    __shared__ float smax[TPB / 32][RPB];
    const int warp = threadIdx.x >> 5;
    if ((threadIdx.x & 31) == 0) {
        #pragma unroll
        for (int r = 0; r < RPB; r++) smax[warp][r] = m[r];
    }
    __syncthreads();

    // 64 threads: thread = r*8 + w reduces row r across the 8 warps
    if (threadIdx.x < (TPB / 32) * RPB) {
        const int r = threadIdx.x >> 3;
        const int w = threadIdx.x & 7;
        float v = smax[w][r];
        #pragma unroll
        for (int off = 4; off; off >>= 1)
            v = fmaxf(v, __shfl_xor_sync(0xffffffffu, v, off));
        if (w == 0) {
            const int i = row0 + r;
            out[i * 3 + 0] = v;
            out[i * 3 + 1] = v;
            out[i * 3 + 2] = v;
        }
    }
}

extern "C" void kernel_launch(void* const* d_in, const int* in_sizes, int n_in,
                              void* d_out, int out_size) {
    const float* x    = (const float*)d_in[0];
    const int*   adj  = (const int*)d_in[1];
    const float* Wphi = (const float*)d_in[2];
    // d_in[3] (W_theta) is unused in the forward pass.
    float* out = (float*)d_out;

    precompute_kernel<<<(NN + 255) / 256, 256>>>(x, Wphi);
    rowmax_kernel<<<NN / RPB, TPB>>>(adj, out);
}

// round 5
// speedup vs baseline: 1.2886x; 1.2456x over previous
#include <cuda_runtime.h>
#include <cstdint>

#define NN 8192
#define NCHUNK (NN / 32)      // 256 chunks of 32 candidates
#define KB 4096               // histogram buckets

// Scratch (device globals — no allocation allowed in kernel_launch)
__device__ float g_s[NN];       // s[j] by original index
__device__ float g_ss[NN];      // s sorted ascending (bucket order)
__device__ float g_ws[NN];      // wmax in sorted order
__device__ int   g_idx[NN];     // original index in sorted order
__device__ float g_cmin[NCHUNK];  // suffix min of s over chunks >= c
__device__ float g_cwub[NCHUNK];  // suffix max of wmax over chunks >= c

// ---------------------------------------------------------------------------
// Kernel 1: single CTA — compute s/wmax, counting-sort by s, chunk suffix bounds
// ---------------------------------------------------------------------------
__global__ __launch_bounds__(1024)
void prep_kernel(const float* __restrict__ x, const float* __restrict__ Wphi) {
    __shared__ int   hist[KB];     // 16 KB: histogram, then inclusive prefix
    __shared__ int   cur[KB];      // 16 KB: scatter cursors
    __shared__ float cmin[NCHUNK];
    __shared__ float cwub[NCHUNK];

    const int t = threadIdx.x;

    // Phase 0: zero histogram
    #pragma unroll
    for (int q = 0; q < KB / 1024; q++) hist[t + q * 1024] = 0;
    __syncthreads();

    // Phase 1: s, wmax, bucket, histogram  (8 elements per thread)
    float sv[NN / 1024], wv[NN / 1024];
    int   bv[NN / 1024];
    #pragma unroll
    for (int q = 0; q < NN / 1024; q++) {
        int j = t + q * 1024;
        float s = x[3 * j + 0] + x[3 * j + 1] + x[3 * j + 2];
        float w0 = Wphi[j], w1 = Wphi[NN + j], w2 = Wphi[2 * NN + j];
        float w = fmaxf(w0, fmaxf(w1, w2));
        g_s[j] = s;
        sv[q] = s; wv[q] = w;
        int b = (int)(s * (KB / 3.0f));
        b = max(0, min(KB - 1, b));
        bv[q] = b;
        atomicAdd(&hist[b], 1);
    }
    __syncthreads();

    // Phase 2: inclusive prefix sum of hist (Hillis-Steele, in-place, 2-sync)
    for (int d = 1; d < KB; d <<= 1) {
        int add[KB / 1024];
        #pragma unroll
        for (int q = 0; q < KB / 1024; q++) {
            int idx = t + q * 1024;
            add[q] = (idx >= d) ? hist[idx - d] : 0;
        }
        __syncthreads();
        #pragma unroll
        for (int q = 0; q < KB / 1024; q++) hist[t + q * 1024] += add[q];
        __syncthreads();
    }
    // cur[b] = exclusive offset
    #pragma unroll
    for (int q = 0; q < KB / 1024; q++) {
        int b = t + q * 1024;
        cur[b] = (b > 0) ? hist[b - 1] : 0;
    }
    __syncthreads();

    // Phase 3: scatter into sorted arrays
    #pragma unroll
    for (int q = 0; q < NN / 1024; q++) {
        int pos = atomicAdd(&cur[bv[q]], 1);
        g_ss[pos]  = sv[q];
        g_ws[pos]  = wv[q];
        g_idx[pos] = t + q * 1024;
    }
    __syncthreads();   // global writes visible CTA-wide after barrier

    // Phase 4: per-chunk min(s) / max(wmax)
    if (t < NCHUNK) {
        float mn =  3.0e38f;
        float mx = -3.0e38f;
        #pragma unroll 8
        for (int q = 0; q < 32; q++) {
            mn = fminf(mn, g_ss[t * 32 + q]);
            mx = fmaxf(mx, g_ws[t * 32 + q]);
        }
        cmin[t] = mn;
        cwub[t] = mx;
    }
    __syncthreads();

    // Phase 5: suffix scan over 256 chunks (in-place, 2-sync per step)
    for (int d = 1; d < NCHUNK; d <<= 1) {
        float vmn = 0.f, vmx = 0.f;
        bool act = (t < NCHUNK && t + d < NCHUNK);
        if (act) { vmn = cmin[t + d]; vmx = cwub[t + d]; }
        __syncthreads();
        if (act) {
            cmin[t] = fminf(cmin[t], vmn);
            cwub[t] = fmaxf(cwub[t], vmx);
        }
        __syncthreads();
    }
    if (t < NCHUNK) {
        g_cmin[t] = cmin[t];
        g_cwub[t] = cwub[t];
    }
}

// ---------------------------------------------------------------------------
// Kernel 2: warp per row — probe sorted candidates with suffix-bound early exit
// ---------------------------------------------------------------------------
__global__ __launch_bounds__(256)
void probe_kernel(const int* __restrict__ adj, float* __restrict__ out) {
    const int lane = threadIdx.x & 31;
    const int warp = threadIdx.x >> 5;
    const int i = blockIdx.x * 8 + warp;

    const float si = g_s[i];
    const int* __restrict__ arow = adj + (size_t)i * NN;

    float best = 0.0f;   // reference max always includes T[i,i] = 0

    for (int c = 0; c < NCHUNK; c++) {
        const int k = c * 32 + lane;
        float sj = g_ss[k];
        float d  = si - sj;
        float contrib = 0.0f;
        if (d > 0.0f) {
            if (__ldg(&arow[g_idx[k]]) != 0)
                contrib = d * g_ws[k];
        }
        // warp max-reduce
        #pragma unroll
        for (int off = 16; off; off >>= 1)
            contrib = fmaxf(contrib, __shfl_xor_sync(0xffffffffu, contrib, off));
        best = fmaxf(best, contrib);

        if (c + 1 < NCHUNK) {
            // Safe suffix bound: no candidate in chunks >= c+1 can exceed this
            float bound = (si - g_cmin[c + 1]) * g_cwub[c + 1];
            if (bound <= best) break;
        }
    }

    if (lane == 0) {
        out[i * 3 + 0] = best;
        out[i * 3 + 1] = best;
        out[i * 3 + 2] = best;
    }
}

extern "C" void kernel_launch(void* const* d_in, const int* in_sizes, int n_in,
                              void* d_out, int out_size) {
    const float* x    = (const float*)d_in[0];
    const int*   adj  = (const int*)d_in[1];
    const float* Wphi = (const float*)d_in[2];
    // d_in[3] (W_theta) is unused in the forward pass.
    float* out = (float*)d_out;

    prep_kernel<<<1, 1024>>>(x, Wphi);
    probe_kernel<<<NN / 8, 256>>>(adj, out);
}

// round 6
// speedup vs baseline: 1.6036x; 1.2445x over previous
#include <cuda_runtime.h>
#include <cstdint>

#define NN 8192
#define NCHUNK (NN / 32)      // 256 chunks of 32 candidates
#define NPAIR (NCHUNK / 2)    // 128 pairs (64 candidates each)
#define KB 4096               // histogram buckets

// Scratch (device globals — no allocation allowed in kernel_launch)
__device__ float g_s[NN];        // s[j] by original index
__device__ float g_ss[NN];       // s in bucket-sorted order
__device__ float g_ws[NN];       // wmax in bucket-sorted order
__device__ int   g_idx[NN];      // original index in bucket-sorted order
__device__ float g_cmin[NCHUNK]; // suffix min of s over chunks >= c
__device__ float g_cwub[NCHUNK]; // suffix max of wmax over chunks >= c

// ---------------------------------------------------------------------------
// Kernel 1: single CTA, 1024 threads — s/wmax, counting-sort by s (bucket
// granularity), per-chunk suffix bounds. Warp-shuffle scans (few barriers).
// ---------------------------------------------------------------------------
__global__ __launch_bounds__(1024)
void prep_kernel(const float* __restrict__ x, const float* __restrict__ Wphi) {
    __shared__ int   hist[KB];
    __shared__ int   cur[KB];
    __shared__ int   warpsums[32];
    __shared__ float cmin_s[NCHUNK];
    __shared__ float cwub_s[NCHUNK];

    const int t    = threadIdx.x;
    const int lane = t & 31;
    const int wid  = t >> 5;

    // Zero histogram
    #pragma unroll
    for (int q = 0; q < KB / 1024; q++) hist[t + q * 1024] = 0;
    __syncthreads();

    // Phase 1: s, wmax, bucket id, histogram (8 elements/thread)
    float sv[NN / 1024], wv[NN / 1024];
    int   bv[NN / 1024];
    #pragma unroll
    for (int q = 0; q < NN / 1024; q++) {
        int j = t + q * 1024;
        float s = x[3 * j + 0] + x[3 * j + 1] + x[3 * j + 2];
        float w0 = Wphi[j], w1 = Wphi[NN + j], w2 = Wphi[2 * NN + j];
        float w = fmaxf(w0, fmaxf(w1, w2));
        g_s[j] = s;
        int b = (int)(s * (KB / 3.0f));
        b = max(0, min(KB - 1, b));
        atomicAdd(&hist[b], 1);
        sv[q] = s; wv[q] = w; bv[q] = b;
    }
    __syncthreads();

    // Phase 2: exclusive scan of hist[4096] -> cur (hierarchical warp scan)
    int4 h = reinterpret_cast<const int4*>(hist)[t];   // buckets 4t..4t+3
    int lsum = h.x + h.y + h.z + h.w;
    int inc = lsum;
    #pragma unroll
    for (int off = 1; off < 32; off <<= 1) {
        int n = __shfl_up_sync(0xffffffffu, inc, off);
        if (lane >= off) inc += n;
    }
    if (lane == 31) warpsums[wid] = inc;
    __syncthreads();
    if (wid == 0) {
        int ws = warpsums[lane];
        int winc = ws;
        #pragma unroll
        for (int off = 1; off < 32; off <<= 1) {
            int n = __shfl_up_sync(0xffffffffu, winc, off);
            if (lane >= off) winc += n;
        }
        warpsums[lane] = winc - ws;   // exclusive warp offset
    }
    __syncthreads();
    {
        int base = warpsums[wid] + (inc - lsum);   // global exclusive offset
        cur[4 * t + 0] = base;
        cur[4 * t + 1] = base + h.x;
        cur[4 * t + 2] = base + h.x + h.y;
        cur[4 * t + 3] = base + h.x + h.y + h.z;
    }
    __syncthreads();

    // Phase 3: scatter into bucket-sorted arrays
    #pragma unroll
    for (int q = 0; q < NN / 1024; q++) {
        int pos = atomicAdd(&cur[bv[q]], 1);
        g_ss[pos]  = sv[q];
        g_ws[pos]  = wv[q];
        g_idx[pos] = t + q * 1024;
    }
    __syncthreads();   // CTA-internal global writes now visible

    // Phase 4: per-chunk min(s) / max(wmax)
    if (t < NCHUNK) {
        float mn =  3.0e38f, mx = -3.0e38f;
        #pragma unroll 8
        for (int q = 0; q < 32; q++) {
            mn = fminf(mn, g_ss[t * 32 + q]);
            mx = fmaxf(mx, g_ws[t * 32 + q]);
        }
        cmin_s[t] = mn;
        cwub_s[t] = mx;
    }
    __syncthreads();

    // Phase 5: suffix scan over 256 chunks — single warp, 8 chunks per lane
    if (t < 32) {
        float lm[8], lw[8];
        float amn = 3.0e38f, amx = -3.0e38f;
        #pragma unroll
        for (int q = 0; q < 8; q++) {
            lm[q] = cmin_s[t * 8 + q];
            lw[q] = cwub_s[t * 8 + q];
            amn = fminf(amn, lm[q]);
            amx = fmaxf(amx, lw[q]);
        }
        // reverse inclusive scan across lanes
        float smn = amn, smx = amx;
        #pragma unroll
        for (int off = 1; off < 32; off <<= 1) {
            float nm = __shfl_down_sync(0xffffffffu, smn, off);
            float nx = __shfl_down_sync(0xffffffffu, smx, off);
            if (lane + off < 32) { smn = fminf(smn, nm); smx = fmaxf(smx, nx); }
        }
        // tail beyond this lane's chunks = inclusive suffix of lane+1
        float tmn = __shfl_down_sync(0xffffffffu, smn, 1);
        float tmx = __shfl_down_sync(0xffffffffu, smx, 1);
        if (lane == 31) { tmn = 3.0e38f; tmx = -3.0e38f; }
        // walk own chunks high -> low
        float rmn = tmn, rmx = tmx;
        #pragma unroll
        for (int q = 7; q >= 0; q--) {
            rmn = fminf(rmn, lm[q]);
            rmx = fmaxf(rmx, lw[q]);
            g_cmin[t * 8 + q] = rmn;
            g_cwub[t * 8 + q] = rmx;
        }
    }
}

// ---------------------------------------------------------------------------
// Kernel 2: warp per row — 64 candidates/iter, prefetch next 64 before reduce
// ---------------------------------------------------------------------------
__global__ __launch_bounds__(256)
void probe_kernel(const int* __restrict__ adj, float* __restrict__ out) {
    const int lane = threadIdx.x & 31;
    const int warp = threadIdx.x >> 5;
    const int i = blockIdx.x * 8 + warp;

    const float si = g_s[i];
    const int* __restrict__ arow = adj + (size_t)i * NN;

    float best = 0.0f;   // reference max always includes T[i,i] = 0

    // Preload pair 0 (candidates 0..63)
    int a0 = __ldg(&arow[g_idx[lane]]);
    int a1 = __ldg(&arow[g_idx[lane + 32]]);

    for (int p = 0; p < NPAIR; p++) {
        // Prefetch next pair's adjacency BEFORE the reduce (overlaps DRAM latency)
        int na0 = 0, na1 = 0;
        if (p + 1 < NPAIR) {
            const int nb = (p + 1) * 64;
            na0 = __ldg(&arow[g_idx[nb + lane]]);
            na1 = __ldg(&arow[g_idx[nb + lane + 32]]);
        }

        const int b = p * 64;
        float c0 = 0.0f, c1 = 0.0f;
        float d0 = si - g_ss[b + lane];
        float d1 = si - g_ss[b + lane + 32];
        if (d0 > 0.0f && a0) c0 = d0 * g_ws[b + lane];
        if (d1 > 0.0f && a1) c1 = d1 * g_ws[b + lane + 32];
        float c = fmaxf(c0, c1);

        #pragma unroll
        for (int off = 16; off; off >>= 1)
            c = fmaxf(c, __shfl_xor_sync(0xffffffffu, c, off));
        best = fmaxf(best, c);

        if (p + 1 < NPAIR) {
            // Safe bound on everything in chunks >= 2(p+1)
            float bound = (si - g_cmin[2 * p + 2]) * g_cwub[2 * p + 2];
            if (bound <= best) break;
            a0 = na0; a1 = na1;
        }
    }

    if (lane == 0) {
        out[i * 3 + 0] = best;
        out[i * 3 + 1] = best;
        out[i * 3 + 2] = best;
    }
}

extern "C" void kernel_launch(void* const* d_in, const int* in_sizes, int n_in,
                              void* d_out, int out_size) {
    const float* x    = (const float*)d_in[0];
    const int*   adj  = (const int*)d_in[1];
    const float* Wphi = (const float*)d_in[2];
    // d_in[3] (W_theta) is unused in the forward pass.
    float* out = (float*)d_out;

    prep_kernel<<<1, 1024>>>(x, Wphi);
    probe_kernel<<<NN / 8, 256>>>(adj, out);
}